// round 11
// baseline (speedup 1.0000x reference)
#include <cuda_runtime.h>
#include <cuda_bf16.h>
#include <math.h>

// ---------------------------------------------------------------------------
// VectorQuantiser forward, GB300 sm_103a
// z [16,64,64,64] f32 (4194304), embedding [1024,64] f32, embed_prob [1024]
// Tokens N = 65536, codes K = 1024, dim D = 64.
// Output (f32, reference order): z_q_out [4194304], loss [1], perplexity [1],
//   new_embedding [65536], embed_prob_new [1024], encoding_indices [65536]
// ---------------------------------------------------------------------------

#define N_TOK 65536
#define K_CODE 1024
#define D_DIM 64

#define OFF_ZQ   0
#define OFF_LOSS 4194304
#define OFF_PERP 4194305
#define OFF_EMB  4194306
#define OFF_EPN  4259842
#define OFF_ENC  4260866

// ---- scratch (static device memory; allocation-free) ----
__device__ float              g_e2[K_CODE];
__device__ unsigned long long g_cbest[K_CODE * 256];   // [code][block]
__device__ int                g_hist[K_CODE];
__device__ float              g_partial[256];

// ---- helpers ----
__device__ __forceinline__ unsigned long long fma_f32x2(
    unsigned long long a, unsigned long long b, unsigned long long c) {
    unsigned long long d;
    asm("fma.rn.f32x2 %0, %1, %2, %3;" : "=l"(d) : "l"(a), "l"(b), "l"(c));
    return d;
}

// ---------------------------------------------------------------------------
// Kernel 1: prep — codebook squared norms (frozen chain) + zero histogram
// ---------------------------------------------------------------------------
__global__ void vq_prep(const float* __restrict__ emb) {
    int k = blockIdx.x * 256 + threadIdx.x;   // grid 4 x 256
    float s = 0.f;
    const float* e = emb + k * D_DIM;
#pragma unroll
    for (int j = 0; j < D_DIM; j++) s = fmaf(e[j], e[j], s);
    g_e2[k] = s;
    g_hist[k] = 0;
}

// ---------------------------------------------------------------------------
// Kernel 2: main — distances + dual argmax + enc + hist + z_q + loss.
// Core chunk loop BIT-IDENTICAL to R9/R10-passing kernels. New epilogue:
// z_q_out + loss computed in-place from register-resident z rows (zpk) and
// the thread's argmax code, with warp-cooperative emb-row staging in the
// union'd chunk smem. Frozen per-element rounding chain throughout.
// ---------------------------------------------------------------------------
__global__ void __launch_bounds__(128, 2) vq_main(
    const float* __restrict__ z, const float* __restrict__ emb,
    float* __restrict__ out) {
    // union: chunk phase uses [e 8192f][e2 128f][sbest 128 u64 = 256f];
    // epilogue staging uses 128*65 = 8320f. Total 8576 floats = 34.3 KB.
    __shared__ __align__(16) float sh_u[8576];
    __shared__ int sh_hist[K_CODE];
    float* sh_e = sh_u;
    float* sh_e2 = sh_u + 8192;
    unsigned long long* sbest = (unsigned long long*)(sh_u + 8320);

    const int tid = threadIdx.x;
    const int lane = tid & 31;
    const int wrp = tid >> 5;
    const int n0 = blockIdx.x * 128 + tid;              // 0..32767
    const int n1 = n0 + 32768;                          // 32768..65535
    const float* zb0 = z + ((size_t)(n0 >> 12) << 18) + (n0 & 4095);
    const float* zb1 = zb0 + ((size_t)8 << 18);         // +8 batches

    const unsigned sb_base = (unsigned)__cvta_generic_to_shared(sbest);

#pragma unroll
    for (int i = 0; i < 8; i++) sh_hist[tid + i * 128] = 0;

    unsigned long long zpk0[32], zpk1[32];
    float zn2a = 0.f, zn2b = 0.f;
#pragma unroll
    for (int t = 0; t < 32; t++) {
        float a0 = zb0[(size_t)(2 * t) << 12];
        float a1 = zb0[(size_t)(2 * t + 1) << 12];
        zn2a = fmaf(a0, a0, zn2a);
        zn2a = fmaf(a1, a1, zn2a);
        asm("mov.b64 %0, {%1, %2};" : "=l"(zpk0[t]) : "f"(a0), "f"(a1));
        float c0 = zb1[(size_t)(2 * t) << 12];
        float c1 = zb1[(size_t)(2 * t + 1) << 12];
        zn2b = fmaf(c0, c0, zn2b);
        zn2b = fmaf(c1, c1, zn2b);
        asm("mov.b64 %0, {%1, %2};" : "=l"(zpk1[t]) : "f"(c0), "f"(c1));
    }
    const float nzn20 = -zn2a;
    const float nzn21 = -zn2b;
    const unsigned ntok0 = ~((unsigned)n0);
    const unsigned ntok1 = ~((unsigned)n1);

    unsigned best_u0 = 0, best_u1 = 0;
    int bestk0 = 0, bestk1 = 0;

    for (int ch = 0; ch < 8; ch++) {
        const int kbase = ch << 7;
        const float4* src = (const float4*)(emb + (ch << 13));
        float4* dst = (float4*)sh_e;
#pragma unroll
        for (int r = 0; r < 16; r++) dst[tid + (r << 7)] = src[tid + (r << 7)];
        sh_e2[tid] = g_e2[kbase + tid];
        sbest[tid] = 0ULL;
        __syncthreads();

#pragma unroll 2
        for (int kc = 0; kc < 128; kc++) {
            float e2 = sh_e2[kc];
            const ulonglong2* ep = (const ulonglong2*)(sh_e + (kc << 6));
            unsigned long long a0 = 0ULL, a1 = 0ULL;    // token0
            unsigned long long b0 = 0ULL, b1 = 0ULL;    // token1
#pragma unroll
            for (int t = 0; t < 8; t++) {
                ulonglong2 e01 = ep[2 * t];       // LDS.128 broadcast
                ulonglong2 e23 = ep[2 * t + 1];
                a0 = fma_f32x2(zpk0[4 * t + 0], e01.x, a0);
                a1 = fma_f32x2(zpk0[4 * t + 1], e01.y, a1);
                b0 = fma_f32x2(zpk1[4 * t + 0], e01.x, b0);
                b1 = fma_f32x2(zpk1[4 * t + 1], e01.y, b1);
                a0 = fma_f32x2(zpk0[4 * t + 2], e23.x, a0);
                a1 = fma_f32x2(zpk0[4 * t + 3], e23.y, a1);
                b0 = fma_f32x2(zpk1[4 * t + 2], e23.x, b0);
                b1 = fma_f32x2(zpk1[4 * t + 3], e23.y, b1);
            }
            float l0, h0, l1, h1, m0, g0, m1, g1;
            asm("mov.b64 {%0,%1}, %2;" : "=f"(l0), "=f"(h0) : "l"(a0));
            asm("mov.b64 {%0,%1}, %2;" : "=f"(l1), "=f"(h1) : "l"(a1));
            asm("mov.b64 {%0,%1}, %2;" : "=f"(m0), "=f"(g0) : "l"(b0));
            asm("mov.b64 {%0,%1}, %2;" : "=f"(m1), "=f"(g1) : "l"(b1));
            float dot0 = (l0 + h0) + (l1 + h1);         // frozen combine
            float dot1 = (m0 + g0) + (m1 + g1);
            float d0 = __fadd_rn(__fsub_rn(nzn20, e2), __fmul_rn(2.0f, dot0));
            float d1 = __fadd_rn(__fsub_rn(nzn21, e2), __fmul_rn(2.0f, dot1));
            int k = kbase + kc;

            unsigned u0 = ~__float_as_uint(d0);         // d<0: monotone key
            unsigned u1 = ~__float_as_uint(d1);
            if (u0 > best_u0) { best_u0 = u0; bestk0 = k; }
            if (u1 > best_u1) { best_u1 = u1; bestk1 = k; }

            unsigned uc = u0 > u1 ? u0 : u1;
            unsigned wmax = __reduce_max_sync(0xFFFFFFFFu, uc);
            unsigned tokn = (u0 == wmax) ? ntok0 : ntok1;
            unsigned pass = (uc == wmax);
            unsigned long long pk = ((unsigned long long)wmax << 32) | tokn;
            asm volatile(
                "{\n\t.reg .pred p;\n\t.reg .u64 t;\n\t"
                "setp.ne.u32 p, %0, 0;\n\t"
                "@p atom.shared.max.u64 t, [%1], %2;\n\t}"
                :: "r"(pass), "r"(sb_base + kc * 8), "l"(pk));
        }
        __syncthreads();
        g_cbest[(size_t)(kbase + tid) * 256 + blockIdx.x] = sbest[tid];
        __syncthreads();
    }

    out[OFF_ENC + n0] = (float)bestk0;
    out[OFF_ENC + n1] = (float)bestk1;
    atomicAdd(&sh_hist[bestk0], 1);
    atomicAdd(&sh_hist[bestk1], 1);

    // ---- epilogue: z_q_out + loss from register-resident z rows ----
    float ls = 0.f;
    // pass 0: tokens n0 (codes bestk0, z in zpk0)
    {
#pragma unroll 4
        for (int j = 0; j < 32; j++) {
            int id = __shfl_sync(0xFFFFFFFFu, bestk0, j);
            float2 ev = *(const float2*)(emb + (id << 6) + lane * 2);
            int row = wrp * 32 + j;
            sh_u[row * 65 + lane * 2]     = ev.x;
            sh_u[row * 65 + lane * 2 + 1] = ev.y;
        }
        __syncwarp();
        const size_t ibase = ((size_t)(n0 >> 12) << 18) + (n0 & 4095);
#pragma unroll
        for (int t = 0; t < 32; t++) {
            float zlo, zhi;
            asm("mov.b64 {%0,%1}, %2;" : "=f"(zlo), "=f"(zhi) : "l"(zpk0[t]));
            float e0 = sh_u[tid * 65 + 2 * t];
            float e1 = sh_u[tid * 65 + 2 * t + 1];
            float df0 = __fsub_rn(e0, zlo);              // frozen chain
            float df1 = __fsub_rn(e1, zhi);
            out[OFF_ZQ + ibase + ((size_t)(2 * t) << 12)] = __fadd_rn(zlo, df0);
            out[OFF_ZQ + ibase + ((size_t)(2 * t + 1) << 12)] = __fadd_rn(zhi, df1);
            ls = fmaf(df0, df0, ls);
            ls = fmaf(df1, df1, ls);
        }
        __syncwarp();
    }
    // pass 1: tokens n1 (codes bestk1, z in zpk1)
    {
#pragma unroll 4
        for (int j = 0; j < 32; j++) {
            int id = __shfl_sync(0xFFFFFFFFu, bestk1, j);
            float2 ev = *(const float2*)(emb + (id << 6) + lane * 2);
            int row = wrp * 32 + j;
            sh_u[row * 65 + lane * 2]     = ev.x;
            sh_u[row * 65 + lane * 2 + 1] = ev.y;
        }
        __syncwarp();
        const size_t ibase = ((size_t)(n1 >> 12) << 18) + (n1 & 4095);
#pragma unroll
        for (int t = 0; t < 32; t++) {
            float zlo, zhi;
            asm("mov.b64 {%0,%1}, %2;" : "=f"(zlo), "=f"(zhi) : "l"(zpk1[t]));
            float e0 = sh_u[tid * 65 + 2 * t];
            float e1 = sh_u[tid * 65 + 2 * t + 1];
            float df0 = __fsub_rn(e0, zlo);
            float df1 = __fsub_rn(e1, zhi);
            out[OFF_ZQ + ibase + ((size_t)(2 * t) << 12)] = __fadd_rn(zlo, df0);
            out[OFF_ZQ + ibase + ((size_t)(2 * t + 1) << 12)] = __fadd_rn(zhi, df1);
            ls = fmaf(df0, df0, ls);
            ls = fmaf(df1, df1, ls);
        }
    }
    // block loss reduction (reuse union smem after full sync)
    __syncthreads();
    sh_u[tid] = ls;
    __syncthreads();
    for (int s = 64; s > 0; s >>= 1) {
        if (tid < s) sh_u[tid] += sh_u[tid + s];
        __syncthreads();
    }
    if (tid == 0) g_partial[blockIdx.x] = sh_u[0];

    // histogram flush
#pragma unroll
    for (int i = 0; i < 8; i++) {
        int v = sh_hist[tid + i * 128];
        if (v) atomicAdd(&g_hist[tid + i * 128], v);
    }
}

// ---------------------------------------------------------------------------
// Kernel 3: per-code best + embed_prob_new + decay + new_embedding (merged).
// ---------------------------------------------------------------------------
__global__ void vq_closest_emb(float* __restrict__ out,
                               const float* __restrict__ z,
                               const float* __restrict__ emb,
                               const float* __restrict__ prob) {
    __shared__ unsigned long long red[64];
    __shared__ int s_cn;
    int k = blockIdx.x;                       // grid 1024 x 64
    int t = threadIdx.x;
    unsigned long long m = 0ULL;
    const unsigned long long* row = g_cbest + (size_t)k * 256;
#pragma unroll
    for (int i = 0; i < 4; i++) {
        unsigned long long v = row[i * 64 + t];
        if (v > m) m = v;
    }
    red[t] = m;
    __syncthreads();
    if (t < 32) {
        unsigned long long v = red[t + 32];
        if (v > m) m = v;
#pragma unroll
        for (int s = 16; s > 0; s >>= 1) {
            unsigned long long o = __shfl_xor_sync(0xFFFFFFFFu, m, s);
            if (o > m) m = o;
        }
        if (t == 0) s_cn = (int)(~((unsigned)m));
    }

    float avg = (float)g_hist[k] * (1.0f / 65536.0f);   // exact /2^16
    float epn = __fadd_rn(__fmul_rn(prob[k], 0.99f), __fmul_rn(0.01f, avg));
    if (t == 0) out[OFF_EPN + k] = epn;
    float a = __fmul_rn(epn, 1024.0f);
    a = __fmul_rn(a, 10.0f);
    a = a / 0.01f;
    float decay = expf(__fsub_rn(-a, 1e-3f));
    float omd = __fsub_rn(1.0f, decay);
    __syncthreads();

    int cn = s_cn;
    int cb = cn >> 12, cp = cn & 4095;
    float zc = z[((size_t)cb << 18) + ((size_t)t << 12) + cp];
    float e = emb[k * D_DIM + t];
    out[OFF_EMB + k * D_DIM + t] =
        __fadd_rn(__fmul_rn(e, omd), __fmul_rn(zc, decay));
}

// ---------------------------------------------------------------------------
// Kernel 4: final — perplexity (from hist) + deterministic loss reduction
// ---------------------------------------------------------------------------
__global__ void vq_final(float* __restrict__ out) {
    __shared__ float redp[1024];
    __shared__ double redl[1024];
    int t = threadIdx.x;                      // grid 1 x 1024
    float avg = (float)g_hist[t] * (1.0f / 65536.0f);
    redp[t] = __fmul_rn(avg, logf(__fadd_rn(avg, 1e-10f)));
    redl[t] = (t < 256) ? (double)g_partial[t] : 0.0;
    __syncthreads();
    for (int s = 512; s > 0; s >>= 1) {
        if (t < s) {
            redp[t] += redp[t + s];
            redl[t] += redl[t + s];
        }
        __syncthreads();
    }
    if (t == 0) {
        out[OFF_PERP] = expf(-redp[0]);
        out[OFF_LOSS] = (float)(1.25 * redl[0] / 4194304.0);  // (1+BETA)*mean
    }
}

// ---------------------------------------------------------------------------
extern "C" void kernel_launch(void* const* d_in, const int* in_sizes, int n_in,
                              void* d_out, int out_size) {
    const float* z = nullptr;
    const float* emb = nullptr;
    const float* prob = nullptr;
    for (int i = 0; i < n_in; i++) {
        if (in_sizes[i] == 4194304) z = (const float*)d_in[i];
        else if (in_sizes[i] == 65536) emb = (const float*)d_in[i];
        else if (in_sizes[i] == 1024) prob = (const float*)d_in[i];
    }
    float* out = (float*)d_out;

    vq_prep<<<4, 256>>>(emb);
    vq_main<<<256, 128>>>(z, emb, out);
    vq_closest_emb<<<1024, 64>>>(out, z, emb, prob);
    vq_final<<<1, 1024>>>(out);
}

// round 12
// speedup vs baseline: 1.0247x; 1.0247x over previous
#include <cuda_runtime.h>
#include <cuda_bf16.h>
#include <math.h>

// ---------------------------------------------------------------------------
// VectorQuantiser forward, GB300 sm_103a
// z [16,64,64,64] f32 (4194304), embedding [1024,64] f32, embed_prob [1024]
// Tokens N = 65536, codes K = 1024, dim D = 64.
// Output (f32, reference order): z_q_out [4194304], loss [1], perplexity [1],
//   new_embedding [65536], embed_prob_new [1024], encoding_indices [65536]
// ---------------------------------------------------------------------------

#define N_TOK 65536
#define K_CODE 1024
#define D_DIM 64

#define OFF_ZQ   0
#define OFF_LOSS 4194304
#define OFF_PERP 4194305
#define OFF_EMB  4194306
#define OFF_EPN  4259842
#define OFF_ENC  4260866

// ---- scratch (static device memory; allocation-free) ----
__device__ float              g_e2[K_CODE];
__device__ unsigned long long g_cbest[K_CODE * 256];   // [code][block]
__device__ __align__(16) int  g_idx[N_TOK];
__device__ int                g_hist[K_CODE];
__device__ float              g_partial[512];

// ---- helpers ----
__device__ __forceinline__ unsigned long long fma_f32x2(
    unsigned long long a, unsigned long long b, unsigned long long c) {
    unsigned long long d;
    asm("fma.rn.f32x2 %0, %1, %2, %3;" : "=l"(d) : "l"(a), "l"(b), "l"(c));
    return d;
}

// ---------------------------------------------------------------------------
// Kernel 1: prep — codebook squared norms (frozen chain) + zero histogram
// ---------------------------------------------------------------------------
__global__ void vq_prep(const float* __restrict__ emb) {
    int k = blockIdx.x * 256 + threadIdx.x;   // grid 4 x 256
    float s = 0.f;
    const float* e = emb + k * D_DIM;
#pragma unroll
    for (int j = 0; j < D_DIM; j++) s = fmaf(e[j], e[j], s);
    g_e2[k] = s;
    g_hist[k] = 0;
}

// ---------------------------------------------------------------------------
// Kernel 2: main — distances + dual argmax + enc + histogram.
// BIT-IDENTICAL to the R10-passing kernel (291.6 us). Untouched.
// ---------------------------------------------------------------------------
__global__ void __launch_bounds__(128, 2) vq_main(
    const float* __restrict__ z, const float* __restrict__ emb,
    float* __restrict__ out) {
    __shared__ __align__(16) float sh_e[128 * D_DIM];   // 32 KB
    __shared__ float sh_e2[128];
    __shared__ __align__(16) unsigned long long sbest[128];
    __shared__ int sh_hist[K_CODE];

    const int tid = threadIdx.x;
    const int n0 = blockIdx.x * 128 + tid;              // 0..32767
    const int n1 = n0 + 32768;                          // 32768..65535
    const float* zb0 = z + ((size_t)(n0 >> 12) << 18) + (n0 & 4095);
    const float* zb1 = zb0 + ((size_t)8 << 18);         // +8 batches

    const unsigned sb_base = (unsigned)__cvta_generic_to_shared(sbest);

#pragma unroll
    for (int i = 0; i < 8; i++) sh_hist[tid + i * 128] = 0;

    unsigned long long zpk0[32], zpk1[32];
    float zn2a = 0.f, zn2b = 0.f;
#pragma unroll
    for (int t = 0; t < 32; t++) {
        float a0 = zb0[(size_t)(2 * t) << 12];
        float a1 = zb0[(size_t)(2 * t + 1) << 12];
        zn2a = fmaf(a0, a0, zn2a);
        zn2a = fmaf(a1, a1, zn2a);
        asm("mov.b64 %0, {%1, %2};" : "=l"(zpk0[t]) : "f"(a0), "f"(a1));
        float c0 = zb1[(size_t)(2 * t) << 12];
        float c1 = zb1[(size_t)(2 * t + 1) << 12];
        zn2b = fmaf(c0, c0, zn2b);
        zn2b = fmaf(c1, c1, zn2b);
        asm("mov.b64 %0, {%1, %2};" : "=l"(zpk1[t]) : "f"(c0), "f"(c1));
    }
    const float nzn20 = -zn2a;
    const float nzn21 = -zn2b;
    const unsigned ntok0 = ~((unsigned)n0);
    const unsigned ntok1 = ~((unsigned)n1);

    unsigned best_u0 = 0, best_u1 = 0;
    int bestk0 = 0, bestk1 = 0;

    for (int ch = 0; ch < 8; ch++) {
        const int kbase = ch << 7;
        const float4* src = (const float4*)(emb + (ch << 13));
        float4* dst = (float4*)sh_e;
#pragma unroll
        for (int r = 0; r < 16; r++) dst[tid + (r << 7)] = src[tid + (r << 7)];
        sh_e2[tid] = g_e2[kbase + tid];
        sbest[tid] = 0ULL;
        __syncthreads();

#pragma unroll 2
        for (int kc = 0; kc < 128; kc++) {
            float e2 = sh_e2[kc];
            const ulonglong2* ep = (const ulonglong2*)(sh_e + (kc << 6));
            unsigned long long a0 = 0ULL, a1 = 0ULL;    // token0
            unsigned long long b0 = 0ULL, b1 = 0ULL;    // token1
#pragma unroll
            for (int t = 0; t < 8; t++) {
                ulonglong2 e01 = ep[2 * t];       // LDS.128 broadcast
                ulonglong2 e23 = ep[2 * t + 1];
                a0 = fma_f32x2(zpk0[4 * t + 0], e01.x, a0);
                a1 = fma_f32x2(zpk0[4 * t + 1], e01.y, a1);
                b0 = fma_f32x2(zpk1[4 * t + 0], e01.x, b0);
                b1 = fma_f32x2(zpk1[4 * t + 1], e01.y, b1);
                a0 = fma_f32x2(zpk0[4 * t + 2], e23.x, a0);
                a1 = fma_f32x2(zpk0[4 * t + 3], e23.y, a1);
                b0 = fma_f32x2(zpk1[4 * t + 2], e23.x, b0);
                b1 = fma_f32x2(zpk1[4 * t + 3], e23.y, b1);
            }
            float l0, h0, l1, h1, m0, g0, m1, g1;
            asm("mov.b64 {%0,%1}, %2;" : "=f"(l0), "=f"(h0) : "l"(a0));
            asm("mov.b64 {%0,%1}, %2;" : "=f"(l1), "=f"(h1) : "l"(a1));
            asm("mov.b64 {%0,%1}, %2;" : "=f"(m0), "=f"(g0) : "l"(b0));
            asm("mov.b64 {%0,%1}, %2;" : "=f"(m1), "=f"(g1) : "l"(b1));
            float dot0 = (l0 + h0) + (l1 + h1);         // frozen combine
            float dot1 = (m0 + g0) + (m1 + g1);
            float d0 = __fadd_rn(__fsub_rn(nzn20, e2), __fmul_rn(2.0f, dot0));
            float d1 = __fadd_rn(__fsub_rn(nzn21, e2), __fmul_rn(2.0f, dot1));
            int k = kbase + kc;

            unsigned u0 = ~__float_as_uint(d0);         // d<0: monotone key
            unsigned u1 = ~__float_as_uint(d1);
            if (u0 > best_u0) { best_u0 = u0; bestk0 = k; }
            if (u1 > best_u1) { best_u1 = u1; bestk1 = k; }

            unsigned uc = u0 > u1 ? u0 : u1;
            unsigned wmax = __reduce_max_sync(0xFFFFFFFFu, uc);
            unsigned tokn = (u0 == wmax) ? ntok0 : ntok1;
            unsigned pass = (uc == wmax);
            unsigned long long pk = ((unsigned long long)wmax << 32) | tokn;
            asm volatile(
                "{\n\t.reg .pred p;\n\t.reg .u64 t;\n\t"
                "setp.ne.u32 p, %0, 0;\n\t"
                "@p atom.shared.max.u64 t, [%1], %2;\n\t}"
                :: "r"(pass), "r"(sb_base + kc * 8), "l"(pk));
        }
        __syncthreads();
        g_cbest[(size_t)(kbase + tid) * 256 + blockIdx.x] = sbest[tid];
        __syncthreads();
    }

    g_idx[n0] = bestk0;
    g_idx[n1] = bestk1;
    out[OFF_ENC + n0] = (float)bestk0;
    out[OFF_ENC + n1] = (float)bestk1;
    atomicAdd(&sh_hist[bestk0], 1);
    atomicAdd(&sh_hist[bestk1], 1);
    __syncthreads();
#pragma unroll
    for (int i = 0; i < 8; i++) {
        int v = sh_hist[tid + i * 128];
        if (v) atomicAdd(&g_hist[tid + i * 128], v);
    }
}

// ---------------------------------------------------------------------------
// Kernel 3: per-code best + embed_prob_new + decay + new_embedding (merged).
// BIT-IDENTICAL to R10.
// ---------------------------------------------------------------------------
__global__ void vq_closest_emb(float* __restrict__ out,
                               const float* __restrict__ z,
                               const float* __restrict__ emb,
                               const float* __restrict__ prob) {
    __shared__ unsigned long long red[64];
    __shared__ int s_cn;
    int k = blockIdx.x;                       // grid 1024 x 64
    int t = threadIdx.x;
    unsigned long long m = 0ULL;
    const unsigned long long* row = g_cbest + (size_t)k * 256;
#pragma unroll
    for (int i = 0; i < 4; i++) {
        unsigned long long v = row[i * 64 + t];
        if (v > m) m = v;
    }
    red[t] = m;
    __syncthreads();
    if (t < 32) {
        unsigned long long v = red[t + 32];
        if (v > m) m = v;
#pragma unroll
        for (int s = 16; s > 0; s >>= 1) {
            unsigned long long o = __shfl_xor_sync(0xFFFFFFFFu, m, s);
            if (o > m) m = o;
        }
        if (t == 0) s_cn = (int)(~((unsigned)m));
    }

    float avg = (float)g_hist[k] * (1.0f / 65536.0f);   // exact /2^16
    float epn = __fadd_rn(__fmul_rn(prob[k], 0.99f), __fmul_rn(0.01f, avg));
    if (t == 0) out[OFF_EPN + k] = epn;
    float a = __fmul_rn(epn, 1024.0f);
    a = __fmul_rn(a, 10.0f);
    a = a / 0.01f;
    float decay = expf(__fsub_rn(-a, 1e-3f));
    float omd = __fsub_rn(1.0f, decay);
    __syncthreads();

    int cn = s_cn;
    int cb = cn >> 12, cp = cn & 4095;
    float zc = z[((size_t)cb << 18) + ((size_t)t << 12) + cp];
    float e = emb[k * D_DIM + t];
    out[OFF_EMB + k * D_DIM + t] =
        __fadd_rn(__fmul_rn(e, omd), __fmul_rn(zc, decay));
}

// ---------------------------------------------------------------------------
// Kernel 4: z_q_out + loss partials — block-staged gather, HIGHER OCCUPANCY.
// 512 blocks x 128 threads; block owns 128 consecutive tokens, smem 33 KB
// (vs R10's 256x256/68KB at 1.7 CTA/SM). Frozen per-element chain.
// ---------------------------------------------------------------------------
__global__ void __launch_bounds__(128) vq_zq_loss(
    float* __restrict__ out, const float* __restrict__ z,
    const float* __restrict__ emb) {
    __shared__ float se[128 * 65];            // 33 KB padded rows
    __shared__ float red[128];

    const int tid = threadIdx.x;
    const int lane = tid & 31;
    const int wrp = tid >> 5;
    const int nbase = blockIdx.x * 128;       // 128 consecutive tokens
    const int b = nbase >> 12;
    const int p = (nbase & 4095) + tid;

    const int myidx = g_idx[nbase + tid];     // coalesced

    // Phase 1: stage emb rows (warp w -> tokens w*32..w*32+31).
#pragma unroll 4
    for (int j = 0; j < 32; j++) {
        int tok = wrp * 32 + j;
        int id = __shfl_sync(0xFFFFFFFFu, myidx, j);
        float2 ev = *(const float2*)(emb + (id << 6) + lane * 2);
        se[tok * 65 + lane * 2]     = ev.x;
        se[tok * 65 + lane * 2 + 1] = ev.y;
    }
    __syncthreads();

    // Phase 2: stream channels, coalesced z/out, conflict-free LDS.
    const size_t ibase = ((size_t)b << 18) + p;
    float ls = 0.f;
#pragma unroll 4
    for (int c = 0; c < 64; c++) {
        size_t i = ibase + ((size_t)c << 12);
        float zv = z[i];
        float ev = se[tid * 65 + c];
        float diff = __fsub_rn(ev, zv);       // frozen chain
        out[OFF_ZQ + i] = __fadd_rn(zv, diff);
        ls = fmaf(diff, diff, ls);
    }
    // warp-shfl loss reduction, then cross-warp
#pragma unroll
    for (int s = 16; s > 0; s >>= 1)
        ls += __shfl_xor_sync(0xFFFFFFFFu, ls, s);
    if (lane == 0) red[wrp] = ls;
    __syncthreads();
    if (tid == 0)
        g_partial[blockIdx.x] = (red[0] + red[1]) + (red[2] + red[3]);
}

// ---------------------------------------------------------------------------
// Kernel 5: final — perplexity + loss, shfl-based (2 syncs, not 10)
// ---------------------------------------------------------------------------
__global__ void vq_final(float* __restrict__ out) {
    __shared__ float sp[32];
    __shared__ double sl[32];
    int t = threadIdx.x;                      // grid 1 x 1024
    int lane = t & 31, wrp = t >> 5;
    float avg = (float)g_hist[t] * (1.0f / 65536.0f);
    float pv = __fmul_rn(avg, logf(__fadd_rn(avg, 1e-10f)));
    double lv = (t < 512) ? (double)g_partial[t] : 0.0;
#pragma unroll
    for (int s = 16; s > 0; s >>= 1) {
        pv += __shfl_xor_sync(0xFFFFFFFFu, pv, s);
        lv += __shfl_xor_sync(0xFFFFFFFFu, lv, s);
    }
    if (lane == 0) { sp[wrp] = pv; sl[wrp] = lv; }
    __syncthreads();
    if (wrp == 0) {
        float p2 = sp[lane];
        double l2 = sl[lane];
#pragma unroll
        for (int s = 16; s > 0; s >>= 1) {
            p2 += __shfl_xor_sync(0xFFFFFFFFu, p2, s);
            l2 += __shfl_xor_sync(0xFFFFFFFFu, l2, s);
        }
        if (lane == 0) {
            out[OFF_PERP] = expf(-p2);
            out[OFF_LOSS] = (float)(1.25 * l2 / 4194304.0);  // (1+BETA)*mean
        }
    }
}

// ---------------------------------------------------------------------------
extern "C" void kernel_launch(void* const* d_in, const int* in_sizes, int n_in,
                              void* d_out, int out_size) {
    const float* z = nullptr;
    const float* emb = nullptr;
    const float* prob = nullptr;
    for (int i = 0; i < n_in; i++) {
        if (in_sizes[i] == 4194304) z = (const float*)d_in[i];
        else if (in_sizes[i] == 65536) emb = (const float*)d_in[i];
        else if (in_sizes[i] == 1024) prob = (const float*)d_in[i];
    }
    float* out = (float*)d_out;

    vq_prep<<<4, 256>>>(emb);
    vq_main<<<256, 128>>>(z, emb, out);
    vq_closest_emb<<<1024, 64>>>(out, z, emb, prob);
    vq_zq_loss<<<512, 128>>>(out, z, emb);
    vq_final<<<1, 1024>>>(out);
}